// round 1
// baseline (speedup 1.0000x reference)
#include <cuda_runtime.h>
#include <math.h>

#define NQ0 1000
#define NQ1 500
#define MP  512          // padded Schur dim (500 -> 512, identity padding)
#define G0P 1024         // padded group-0 count
#define NB  64           // Cholesky panel width
#define NPAN (MP/NB)     // 8 panels
#define NMAX 8192

// ---------------- device scratch (static: no allocations allowed) ----------
static __device__ float g_S[MP*MP];               // Schur matrix / Cholesky L (row-major, lda=MP)
static __device__ float g_Ldiag[NPAN*NB*NB];      // factored diagonal blocks
static __device__ float g_n0[G0P], g_s0[G0P], g_w0[G0P], g_ws0[G0P];
static __device__ float g_n1[MP],  g_s1[MP];
static __device__ float g_u[MP];                  // u1 vector
static __device__ int   g_off[G0P+1];
static __device__ int   g_cur[G0P];
static __device__ unsigned short g_csr[NMAX];     // idx1 grouped by idx0
static __device__ int   g_i0[NMAX], g_i1[NMAX];
static __device__ double g_rTr, g_ldD0, g_q0;
static __device__ int   g_is64;

// ---------------- helpers ----------------
__device__ __forceinline__ void block_reduce_add2(double v1, double v2,
                                                  double* o1, double* o2) {
    __shared__ double s1[32], s2[32];
    int lane = threadIdx.x & 31, wid = threadIdx.x >> 5;
    int nw = (blockDim.x + 31) >> 5;
    #pragma unroll
    for (int o = 16; o; o >>= 1) {
        v1 += __shfl_down_sync(0xffffffffu, v1, o);
        v2 += __shfl_down_sync(0xffffffffu, v2, o);
    }
    if (lane == 0) { s1[wid] = v1; s2[wid] = v2; }
    __syncthreads();
    if (wid == 0) {
        v1 = (lane < nw) ? s1[lane] : 0.0;
        v2 = (lane < nw) ? s2[lane] : 0.0;
        #pragma unroll
        for (int o = 16; o; o >>= 1) {
            v1 += __shfl_down_sync(0xffffffffu, v1, o);
            v2 += __shfl_down_sync(0xffffffffu, v2, o);
        }
        if (lane == 0) {
            if (o1) atomicAdd(o1, v1);
            if (o2) atomicAdd(o2, v2);
        }
    }
}

// ---------------- K1: zero scratch + detect int64 vs int32 indices ---------
__global__ void k_zero(const void* z0) {
    int i = blockIdx.x * blockDim.x + threadIdx.x;
    int stride = gridDim.x * blockDim.x;
    for (int t = i; t < MP*MP; t += stride) g_S[t] = 0.f;
    if (i < G0P) { g_n0[i] = 0.f; g_s0[i] = 0.f; g_cur[i] = 0; }
    if (i < MP)  { g_n1[i] = 0.f; g_s1[i] = 0.f; }
    if (i == 0) {
        g_rTr = 0.0; g_ldD0 = 0.0; g_q0 = 0.0; g_off[0] = 0;
        // Detect 8-byte indices: odd 32-bit words are all-zero high halves.
        const unsigned int* w = (const unsigned int*)z0;
        int all0 = 1;
        for (int k = 1; k < 128; k += 2) if (w[k]) { all0 = 0; break; }
        g_is64 = all0;
    }
}

// ---------------- K2: per-sample scatter: counts, group sums, rTr ----------
__global__ void k_scatter(const float* __restrict__ yt, const float* __restrict__ yp,
                          const void* z0, const void* z1, int n) {
    int i = blockIdx.x * blockDim.x + threadIdx.x;
    float r = 0.f;
    if (i < n && i < NMAX) {
        r = yt[i] - yp[i];
        int a, b;
        if (g_is64) {
            a = (int)((const long long*)z0)[i];
            b = (int)((const long long*)z1)[i];
        } else {
            a = ((const int*)z0)[i];
            b = ((const int*)z1)[i];
        }
        if ((unsigned)a < (unsigned)NQ0 && (unsigned)b < (unsigned)NQ1) {
            g_i0[i] = a; g_i1[i] = b;
            atomicAdd(&g_n0[a], 1.f); atomicAdd(&g_s0[a], r);
            atomicAdd(&g_n1[b], 1.f); atomicAdd(&g_s1[b], r);
        } else { g_i0[i] = 0; g_i1[i] = 0; r = 0.f; }
    }
    block_reduce_add2((double)r * (double)r, 0.0, &g_rTr, 0);
}

// ---------------- K3: w0, logdet(D0), q0, S diagonal, u base ---------------
__global__ void k_prep(const float* __restrict__ sig2e, const float* __restrict__ sig2bs) {
    int i = blockIdx.x * blockDim.x + threadIdx.x;   // 0..1535
    float e = sig2e[0], b0 = sig2bs[0], b1 = sig2bs[1];
    double ld = 0.0, q = 0.0;
    if (i < G0P) {
        float n0 = g_n0[i];
        float d0 = e + b0 * n0;
        float w  = 1.f / d0;
        g_w0[i] = w; g_ws0[i] = g_s0[i] * w;
        if (i < NQ0) {
            ld = log((double)d0);
            q  = (double)b0 * (double)g_s0[i] * (double)g_s0[i] * (double)w;
        }
    } else {
        int j = i - G0P;
        if (j < MP) {
            if (j < NQ1) {
                g_S[j*MP + j] = e + b1 * g_n1[j];
                g_u[j] = sqrtf(b1) * g_s1[j];
            } else {
                g_S[j*MP + j] = 1.f;   // identity padding
                g_u[j] = 0.f;
            }
        }
    }
    block_reduce_add2(ld, q, &g_ldD0, &g_q0);
}

// ---------------- K4: prefix sum over group-0 counts ----------------------
__global__ void k_scan() {
    __shared__ int sm[G0P];
    int t = threadIdx.x;
    sm[t] = (int)g_n0[t];
    __syncthreads();
    for (int d = 1; d < G0P; d <<= 1) {
        int v = (t >= d) ? sm[t - d] : 0;
        __syncthreads();
        sm[t] += v;
        __syncthreads();
    }
    g_off[t + 1] = sm[t];
    if (t == 0) g_off[0] = 0;
}

// ---------------- K5: CSR scatter + u1 correction --------------------------
__global__ void k_csr(const float* __restrict__ sig2bs, int n) {
    int i = blockIdx.x * blockDim.x + threadIdx.x;
    if (i >= n || i >= NMAX) return;
    int a = g_i0[i], b = g_i1[i];
    int p = atomicAdd(&g_cur[a], 1);
    g_csr[g_off[a] + p] = (unsigned short)b;
    float b0 = sig2bs[0], b1 = sig2bs[1];
    atomicAdd(&g_u[b], -sqrtf(b1) * b0 * g_ws0[a]);
}

// ---------------- K6: sparse rank-accumulation of Schur off-diagonal -------
// S -= b0*b1 * C^T D0^{-1} C, built from all ordered sample pairs per group.
__global__ void k_pairs(const float* __restrict__ sig2bs) {
    int w = (blockIdx.x * blockDim.x + threadIdx.x) >> 5;
    int lane = threadIdx.x & 31;
    if (w >= NQ0) return;
    int lo = g_off[w], hi = g_off[w + 1];
    int len = hi - lo;
    if (len == 0) return;
    float coef = -sig2bs[0] * sig2bs[1] * g_w0[w];
    int tot = len * len;
    for (int t = lane; t < tot; t += 32) {
        int a = g_csr[lo + t / len];
        int b = g_csr[lo + t % len];
        atomicAdd(&g_S[a * MP + b], coef);
    }
}

// ---------------- K7: Cholesky panel (diag factor + TRSM) ------------------
__global__ __launch_bounds__(256) void k_panel(int p) {
    __shared__ float Ld[NB][NB + 1];
    __shared__ float dinv[NB];
    __shared__ float A[NB][NB + 1];
    int tid = threadIdx.x;
    int c0 = p * NB;
    // every block factors the diagonal block redundantly (in smem, from gmem)
    for (int t = tid; t < NB * NB; t += 256)
        Ld[t >> 6][t & 63] = g_S[(c0 + (t >> 6)) * MP + c0 + (t & 63)];
    __syncthreads();
    for (int k = 0; k < NB; k++) {
        if (tid == 0) { float v = sqrtf(Ld[k][k]); Ld[k][k] = v; dinv[k] = 1.f / v; }
        __syncthreads();
        for (int i = k + 1 + tid; i < NB; i += 256) Ld[i][k] *= dinv[k];
        __syncthreads();
        int q = tid >> 6, tx = tid & 63;
        for (int i = k + 1 + q; i < NB; i += 4)
            if (tx > k && tx <= i) Ld[i][tx] -= Ld[i][k] * Ld[tx][k];
        __syncthreads();
    }
    if (blockIdx.x == 0) {
        for (int t = tid; t < NB * NB; t += 256)
            g_Ldiag[p * NB * NB + t] = Ld[t >> 6][t & 63];
    } else {
        int r0 = c0 + NB * blockIdx.x;
        for (int t = tid; t < NB * NB; t += 256)
            A[t >> 6][t & 63] = g_S[(r0 + (t >> 6)) * MP + c0 + (t & 63)];
        __syncthreads();
        if (tid < NB) {
            int r = tid;
            for (int j = 0; j < NB; j++) {
                float a = A[r][j];
                float p0 = 0, p1 = 0, p2 = 0, p3 = 0;
                int c = 0;
                for (; c + 4 <= j; c += 4) {
                    p0 += A[r][c]     * Ld[j][c];
                    p1 += A[r][c + 1] * Ld[j][c + 1];
                    p2 += A[r][c + 2] * Ld[j][c + 2];
                    p3 += A[r][c + 3] * Ld[j][c + 3];
                }
                for (; c < j; c++) p0 += A[r][c] * Ld[j][c];
                A[r][j] = (a - ((p0 + p1) + (p2 + p3))) * dinv[j];
            }
        }
        __syncthreads();
        for (int t = tid; t < NB * NB; t += 256)
            g_S[(r0 + (t >> 6)) * MP + c0 + (t & 63)] = A[t >> 6][t & 63];
    }
}

// ---------------- K8: SYRK trailing update (lower-triangle tiles) ----------
__global__ __launch_bounds__(256) void k_syrk(int p) {
    int idx = blockIdx.x, bi = 0;
    while (idx >= bi + 1) { idx -= bi + 1; bi++; }
    int bj = idx;
    int row0 = (p + 1) * NB, c0 = p * NB;
    int rI = row0 + bi * NB, rJ = row0 + bj * NB;
    __shared__ float Li[NB][NB + 1], Lj[NB][NB + 1];
    int tid = threadIdx.x;
    for (int t = tid; t < NB * NB; t += 256) {
        int i = t >> 6, k = t & 63;
        Li[i][k] = g_S[(rI + i) * MP + c0 + k];
        Lj[i][k] = g_S[(rJ + i) * MP + c0 + k];
    }
    __syncthreads();
    int tx = tid & 15, ty = tid >> 4;
    float acc[4][4] = {};
    for (int k = 0; k < NB; k++) {
        float a[4], b[4];
        #pragma unroll
        for (int u = 0; u < 4; u++) a[u] = Li[ty * 4 + u][k];
        #pragma unroll
        for (int v = 0; v < 4; v++) b[v] = Lj[tx * 4 + v][k];
        #pragma unroll
        for (int u = 0; u < 4; u++)
            #pragma unroll
            for (int v = 0; v < 4; v++) acc[u][v] += a[u] * b[v];
    }
    #pragma unroll
    for (int u = 0; u < 4; u++)
        #pragma unroll
        for (int v = 0; v < 4; v++)
            g_S[(rI + ty * 4 + u) * MP + rJ + tx * 4 + v] -= acc[u][v];
}

// ---------------- K9: triangular solves + logdet + final assembly ----------
__global__ __launch_bounds__(512) void k_finish(const float* __restrict__ sig2e,
                                                const float* __restrict__ sig2bs,
                                                float* __restrict__ out, int n) {
    __shared__ float ub[MP];
    __shared__ float Ld[NB][NB + 1];
    __shared__ float logs[NB];
    __shared__ double dred[16];
    int tid = threadIdx.x;
    ub[tid] = g_u[tid];
    if (tid < NB) logs[tid] = 0.f;
    __syncthreads();
    // forward: L y = u
    for (int p = 0; p < NPAN; p++) {
        for (int t = tid; t < NB * NB; t += 512)
            Ld[t >> 6][t & 63] = g_Ldiag[p * NB * NB + t];
        __syncthreads();
        if (tid < NB) logs[tid] += logf(Ld[tid][tid]);
        if (tid < 32) {
            for (int j = 0; j < NB; j++) {
                float s = 0.f;
                if (tid < j) s += Ld[j][tid] * ub[p * NB + tid];
                int c = tid + 32;
                if (c < j) s += Ld[j][c] * ub[p * NB + c];
                #pragma unroll
                for (int o = 16; o; o >>= 1) s += __shfl_down_sync(0xffffffffu, s, o);
                if (tid == 0) ub[p * NB + j] = (ub[p * NB + j] - s) / Ld[j][j];
                __syncwarp();
            }
        }
        __syncthreads();
        int i = (p + 1) * NB + tid;
        if (i < MP) {
            const float* row = &g_S[i * MP + p * NB];
            float a0 = 0, a1 = 0, a2 = 0, a3 = 0;
            #pragma unroll
            for (int c = 0; c < NB; c += 4) {
                a0 += row[c]     * ub[p * NB + c];
                a1 += row[c + 1] * ub[p * NB + c + 1];
                a2 += row[c + 2] * ub[p * NB + c + 2];
                a3 += row[c + 3] * ub[p * NB + c + 3];
            }
            ub[i] -= ((a0 + a1) + (a2 + a3));
        }
        __syncthreads();
    }
    // backward: L^T x = y (in place)
    for (int p = NPAN - 1; p >= 0; p--) {
        for (int t = tid; t < NB * NB; t += 512)
            Ld[t >> 6][t & 63] = g_Ldiag[p * NB * NB + t];
        __syncthreads();
        if (tid < 32) {
            for (int j = NB - 1; j >= 0; j--) {
                float s = 0.f;
                int c = j + 1 + tid;
                if (c < NB) s += Ld[c][j] * ub[p * NB + c];
                c = j + 33 + tid;
                if (c < NB) s += Ld[c][j] * ub[p * NB + c];
                #pragma unroll
                for (int o = 16; o; o >>= 1) s += __shfl_down_sync(0xffffffffu, s, o);
                if (tid == 0) ub[p * NB + j] = (ub[p * NB + j] - s) / Ld[j][j];
                __syncwarp();
            }
        }
        __syncthreads();
        if (tid < p * NB) {
            float a0 = 0, a1 = 0, a2 = 0, a3 = 0;
            #pragma unroll
            for (int j = 0; j < NB; j += 4) {
                a0 += g_S[(p * NB + j)     * MP + tid] * ub[p * NB + j];
                a1 += g_S[(p * NB + j + 1) * MP + tid] * ub[p * NB + j + 1];
                a2 += g_S[(p * NB + j + 2) * MP + tid] * ub[p * NB + j + 2];
                a3 += g_S[(p * NB + j + 3) * MP + tid] * ub[p * NB + j + 3];
            }
            ub[tid] -= ((a0 + a1) + (a2 + a3));
        }
        __syncthreads();
    }
    // quad1 = u1^T x
    double d = (double)g_u[tid] * (double)ub[tid];
    int lane = tid & 31, wid = tid >> 5;
    #pragma unroll
    for (int o = 16; o; o >>= 1) d += __shfl_down_sync(0xffffffffu, d, o);
    if (lane == 0) dred[wid] = d;
    __syncthreads();
    if (tid == 0) {
        double quad1 = 0.0;
        for (int k = 0; k < 16; k++) quad1 += dred[k];
        double lds = 0.0;
        for (int k = 0; k < NB; k++) lds += (double)logs[k];
        lds *= 2.0;
        double e = (double)sig2e[0];
        double logdetV = (double)(n - (NQ0 + NQ1)) * log(e) + g_ldD0 + lds;
        double quad = (g_rTr - g_q0 - quad1) / e;
        double loss = 0.5 * (double)n * 1.8378770664093454836
                    + 0.5 * logdetV + 0.5 * quad;
        out[0] = (float)loss;
    }
}

// ---------------- host launcher --------------------------------------------
extern "C" void kernel_launch(void* const* d_in, const int* in_sizes, int n_in,
                              void* d_out, int out_size) {
    const float* y_true = (const float*)d_in[0];
    const float* y_pred = (const float*)d_in[1];
    const void*  z0     = d_in[2];
    const void*  z1     = d_in[3];
    const float* sig2e  = (const float*)d_in[4];
    const float* sig2bs = (const float*)d_in[5];
    float* out = (float*)d_out;
    int n = in_sizes[0];

    k_zero<<<256, 256>>>(z0);
    k_scatter<<<(n + 255) / 256, 256>>>(y_true, y_pred, z0, z1, n);
    k_prep<<<6, 256>>>(sig2e, sig2bs);
    k_scan<<<1, G0P>>>();
    k_csr<<<(n + 255) / 256, 256>>>(sig2bs, n);
    k_pairs<<<(NQ0 + 7) / 8, 256>>>(sig2bs);
    for (int p = 0; p < NPAN; p++) {
        k_panel<<<NPAN - p, 256>>>(p);
        int T = NPAN - 1 - p;
        if (T > 0) k_syrk<<<T * (T + 1) / 2, 256>>>(p);
    }
    k_finish<<<1, 512>>>(sig2e, sig2bs, out, n);
}